// round 1
// baseline (speedup 1.0000x reference)
#include <cuda_runtime.h>
#include <cuda_bf16.h>
#include <cstdint>

// Problem constants (fixed by the dataset)
#define NN   50000
#define EE   800000
#define FIN  128
#define HH   4
#define DHH  64
#define HID  256   // HH*DHH

// ---------------- static device scratch (no allocation allowed) ----------------
__device__ float    g_feat[(size_t)NN * HID];
__device__ float    g_res [(size_t)NN * HID];
__device__ float    g_h1  [(size_t)NN * HID];
__device__ float    g_h2  [(size_t)NN * HID];
__device__ float    g_out [(size_t)NN * HID];
__device__ float    g_el  [(size_t)NN * HH];
__device__ float    g_er  [(size_t)NN * HH];
__device__ unsigned g_menc[(size_t)NN * HH];
__device__ float    g_mf  [(size_t)NN * HH];
__device__ float    g_den [(size_t)NN * HH];
__device__ float    g_e   [(size_t)EE * HH];
__device__ float    g_ex  [(size_t)EE * HH];

// ---------------- GEMM: C[M,N] = A[M,K] @ B[K,N], fp32 ----------------
// BM=BN=64, BK=16, 256 threads, 4x4 microtile per thread.
__global__ void sgemm64(const float* __restrict__ A, const float* __restrict__ B,
                        float* __restrict__ C, int M, int K, int N)
{
    __shared__ float As[16][64];
    __shared__ float Bs[16][64];
    int tid = threadIdx.x;
    int tx = tid & 15;       // 0..15 -> col group
    int ty = tid >> 4;       // 0..15 -> row group
    int rowBase = blockIdx.y * 64;
    int colBase = blockIdx.x * 64;

    int aRow  = tid >> 2;        // 0..63
    int aCol4 = (tid & 3) * 4;   // 0,4,8,12
    int bRow  = tid >> 4;        // 0..15
    int bCol4 = (tid & 15) * 4;  // 0..60

    float acc[4][4];
#pragma unroll
    for (int i = 0; i < 4; i++)
#pragma unroll
        for (int j = 0; j < 4; j++) acc[i][j] = 0.f;

    for (int kt = 0; kt < K; kt += 16) {
        float4 av = make_float4(0.f, 0.f, 0.f, 0.f);
        int gr = rowBase + aRow;
        if (gr < M) av = *(const float4*)(A + (size_t)gr * K + kt + aCol4);
        As[aCol4 + 0][aRow] = av.x;
        As[aCol4 + 1][aRow] = av.y;
        As[aCol4 + 2][aRow] = av.z;
        As[aCol4 + 3][aRow] = av.w;

        float4 bv = *(const float4*)(B + (size_t)(kt + bRow) * N + colBase + bCol4);
        *(float4*)&Bs[bRow][bCol4] = bv;

        __syncthreads();
#pragma unroll
        for (int k = 0; k < 16; k++) {
            float am[4], bn[4];
#pragma unroll
            for (int i = 0; i < 4; i++) am[i] = As[k][ty * 4 + i];
#pragma unroll
            for (int j = 0; j < 4; j++) bn[j] = Bs[k][tx * 4 + j];
#pragma unroll
            for (int i = 0; i < 4; i++)
#pragma unroll
                for (int j = 0; j < 4; j++) acc[i][j] += am[i] * bn[j];
        }
        __syncthreads();
    }

#pragma unroll
    for (int i = 0; i < 4; i++) {
        int gr = rowBase + ty * 4 + i;
        if (gr < M) {
            float4 v = make_float4(acc[i][0], acc[i][1], acc[i][2], acc[i][3]);
            *(float4*)(C + (size_t)gr * N + colBase + tx * 4) = v;
        }
    }
}

// ---------------- attention logits: el[n,h] = sum_d feat[n,h,d]*al[h,d] ----------------
// one block (256 threads) per node; al/ar are [H*DH]=256 flat, matching feat row layout.
__global__ void attn_logits(const float* __restrict__ feat,
                            const float* __restrict__ al, const float* __restrict__ ar,
                            float* __restrict__ el, float* __restrict__ er)
{
    int n = blockIdx.x;
    int t = threadIdx.x;
    float f = feat[(size_t)n * HID + t];
    float a = f * al[t];
    float b = f * ar[t];
#pragma unroll
    for (int o = 16; o; o >>= 1) {
        a += __shfl_down_sync(0xffffffffu, a, o);
        b += __shfl_down_sync(0xffffffffu, b, o);
    }
    __shared__ float sa[8], sb[8];
    int w = t >> 5;
    if ((t & 31) == 0) { sa[w] = a; sb[w] = b; }
    __syncthreads();
    if (t < 4) {
        el[(size_t)n * HH + t] = sa[2 * t] + sa[2 * t + 1];
        er[(size_t)n * HH + t] = sb[2 * t] + sb[2 * t + 1];
    }
}

// float -> order-preserving unsigned encoding (all finite encodings > 0)
__device__ __forceinline__ unsigned enc_f(float v) {
    unsigned b = __float_as_uint(v);
    return (b & 0x80000000u) ? ~b : (b | 0x80000000u);
}
__device__ __forceinline__ float dec_f(unsigned u) {
    unsigned b = (u & 0x80000000u) ? (u ^ 0x80000000u) : ~u;
    return __uint_as_float(b);
}

// ---------------- edge pass 1: e = leaky(el[src]+er[dst]); atomicMax m[dst] ----------------
__global__ void edge_max_k(const int* __restrict__ src, const int* __restrict__ dst,
                           const float* __restrict__ el, const float* __restrict__ er,
                           float* __restrict__ eo, unsigned* __restrict__ menc, int EH)
{
    int i = blockIdx.x * blockDim.x + threadIdx.x;
    if (i >= EH) return;
    int e = i >> 2, h = i & 3;
    int s = src[e], d = dst[e];
    float v = el[(size_t)s * HH + h] + er[(size_t)d * HH + h];
    v = (v > 0.f) ? v : 0.2f * v;
    eo[i] = v;
    atomicMax(&menc[(size_t)d * HH + h], enc_f(v));
}

__global__ void finalize_m_k(const unsigned* __restrict__ menc, float* __restrict__ mf, int n)
{
    int i = blockIdx.x * blockDim.x + threadIdx.x;
    if (i >= n) return;
    unsigned u = menc[i];
    mf[i] = (u == 0u) ? 0.f : dec_f(u);
}

// ---------------- edge pass 2: ex = exp(e - m[dst]); atomicAdd denom[dst] ----------------
__global__ void edge_exp_k(const int* __restrict__ dst,
                           const float* __restrict__ e_in, const float* __restrict__ mf,
                           float* __restrict__ ex_out, float* __restrict__ den, int EH)
{
    int i = blockIdx.x * blockDim.x + threadIdx.x;
    if (i >= EH) return;
    int e = i >> 2, h = i & 3;
    int d = dst[e];
    float ex = expf(e_in[i] - mf[(size_t)d * HH + h]);
    ex_out[i] = ex;
    atomicAdd(&den[(size_t)d * HH + h], ex);
}

// ---------------- edge pass 3: out[dst] += alpha * feat[src], warp per edge ----------------
// 64 float4 per edge; each lane does 2 float4 vector REDs.
__global__ void edge_agg_k(const int* __restrict__ src, const int* __restrict__ dst,
                           const float* __restrict__ feat, const float* __restrict__ ex,
                           const float* __restrict__ den, float* __restrict__ out, int E)
{
    int w = (blockIdx.x * blockDim.x + threadIdx.x) >> 5;
    int lane = threadIdx.x & 31;
    if (w >= E) return;
    int s = src[w], d = dst[w];
    const float4* f4 = (const float4*)feat + (size_t)s * 64;
    float4* o4 = (float4*)out + (size_t)d * 64;
#pragma unroll
    for (int r = 0; r < 2; r++) {
        int j = lane + r * 32;       // 0..63 float4 index within the row
        int h = j >> 4;              // head
        float a = ex[(size_t)w * HH + h] / fmaxf(den[(size_t)d * HH + h], 1e-16f);
        float4 f = f4[j];
        float4* p = o4 + j;
        asm volatile("red.global.add.v4.f32 [%0], {%1,%2,%3,%4};"
                     :: "l"(p), "f"(f.x * a), "f"(f.y * a), "f"(f.z * a), "f"(f.w * a)
                     : "memory");
    }
}

// ---------------- node finalize (layers 0,1): h = relu(out + res + b) ----------------
__global__ void finalize01_k(const float* __restrict__ out, const float* __restrict__ res,
                             const float* __restrict__ b, float* __restrict__ hnext, int n)
{
    int i = blockIdx.x * blockDim.x + threadIdx.x;
    if (i >= n) return;
    float v = out[i] + res[i] + b[i & (HID - 1)];
    hnext[i] = fmaxf(v, 0.f);
}

// ---------------- final layer: mean over heads of (out + res + b2) ----------------
__global__ void finalize2_k(const float* __restrict__ out, const float* __restrict__ res,
                            const float* __restrict__ b, float* __restrict__ y, int n)
{
    int i = blockIdx.x * blockDim.x + threadIdx.x;  // over NN*DHH
    if (i >= n) return;
    int node = i / DHH;
    int d = i - node * DHH;
    float s = 0.f;
#pragma unroll
    for (int h = 0; h < HH; h++) {
        size_t idx = (size_t)node * HID + h * DHH + d;
        s += out[idx] + res[idx] + b[h * DHH + d];
    }
    y[i] = s * 0.25f;
}

extern "C" void kernel_launch(void* const* d_in, const int* in_sizes, int n_in,
                              void* d_out, int out_size)
{
    const float* x   = (const float*)d_in[0];
    const int*   ei  = (const int*)d_in[1];
    const int E  = in_sizes[1] / 2;
    const int Nn = in_sizes[0] / FIN;
    const int* src = ei;
    const int* dst = ei + E;
    const float* W[3]   = {(const float*)d_in[2], (const float*)d_in[3], (const float*)d_in[4]};
    const float* al[3]  = {(const float*)d_in[5], (const float*)d_in[6], (const float*)d_in[7]};
    const float* ar[3]  = {(const float*)d_in[8], (const float*)d_in[9], (const float*)d_in[10]};
    const float* bb[3]  = {(const float*)d_in[11], (const float*)d_in[12], (const float*)d_in[13]};
    const float* resW0  = (const float*)d_in[14];

    float *feat, *res, *h1, *h2, *out, *el, *er, *mf, *den, *ebuf, *exbuf;
    unsigned* menc;
    cudaGetSymbolAddress((void**)&feat, g_feat);
    cudaGetSymbolAddress((void**)&res,  g_res);
    cudaGetSymbolAddress((void**)&h1,   g_h1);
    cudaGetSymbolAddress((void**)&h2,   g_h2);
    cudaGetSymbolAddress((void**)&out,  g_out);
    cudaGetSymbolAddress((void**)&el,   g_el);
    cudaGetSymbolAddress((void**)&er,   g_er);
    cudaGetSymbolAddress((void**)&mf,   g_mf);
    cudaGetSymbolAddress((void**)&den,  g_den);
    cudaGetSymbolAddress((void**)&ebuf, g_e);
    cudaGetSymbolAddress((void**)&exbuf,g_ex);
    cudaGetSymbolAddress((void**)&menc, g_menc);

    const int EH = E * HH;
    const int MB = (Nn + 63) / 64;
    const dim3 gemmGrid(HID / 64, MB);
    const int NH = Nn * HH;
    const size_t featBytes = (size_t)Nn * HID * sizeof(float);

    auto edge_phase = [&](const float* fcur, const float* alp, const float* arp) {
        attn_logits<<<Nn, 256>>>(fcur, alp, arp, el, er);
        cudaMemsetAsync(menc, 0, (size_t)NH * sizeof(unsigned), 0);
        cudaMemsetAsync(den,  0, (size_t)NH * sizeof(float), 0);
        cudaMemsetAsync(out,  0, featBytes, 0);
        edge_max_k<<<(EH + 255) / 256, 256>>>(src, dst, el, er, ebuf, menc, EH);
        finalize_m_k<<<(NH + 255) / 256, 256>>>(menc, mf, NH);
        edge_exp_k<<<(EH + 255) / 256, 256>>>(dst, ebuf, mf, exbuf, den, EH);
        edge_agg_k<<<(E * 32 + 255) / 256, 256>>>(src, dst, fcur, exbuf, den, out, E);
    };

    // ---- Layer 0 ----
    sgemm64<<<gemmGrid, 256>>>(x, W[0],   feat, Nn, FIN, HID);
    sgemm64<<<gemmGrid, 256>>>(x, resW0,  res,  Nn, FIN, HID);
    edge_phase(feat, al[0], ar[0]);
    finalize01_k<<<((Nn * HID) + 255) / 256, 256>>>(out, res, bb[0], h1, Nn * HID);

    // ---- Layer 1 ----
    sgemm64<<<gemmGrid, 256>>>(h1, W[1], feat, Nn, HID, HID);
    edge_phase(feat, al[1], ar[1]);
    finalize01_k<<<((Nn * HID) + 255) / 256, 256>>>(out, h1, bb[1], h2, Nn * HID);

    // ---- Layer 2 ----
    sgemm64<<<gemmGrid, 256>>>(h2, W[2], feat, Nn, HID, HID);
    edge_phase(feat, al[2], ar[2]);
    finalize2_k<<<((Nn * DHH) + 255) / 256, 256>>>(out, h2, bb[2], (float*)d_out, Nn * DHH);
}

// round 2
// speedup vs baseline: 1.8204x; 1.8204x over previous
#include <cuda_runtime.h>
#include <cstdint>

// Problem constants (fixed by the dataset)
#define NN   50000
#define EE   800000
#define FIN  128
#define HH   4
#define DHH  64
#define HID  256   // HH*DHH

// ---------------- static device scratch ----------------
__device__ float g_feat[(size_t)NN * HID];
__device__ float g_res [(size_t)NN * HID];
__device__ float g_h1  [(size_t)NN * HID];
__device__ float g_h2  [(size_t)NN * HID];
__device__ float g_el  [(size_t)NN * HH];
__device__ float g_er  [(size_t)NN * HH];
__device__ int   g_deg   [NN];
__device__ int   g_rowptr[NN + 1];
__device__ int   g_cursor[NN];
__device__ int   g_esrc  [EE];

// ================= GEMM: C[M,N] = A @ B, fp32 via 3xTF32 tensor-core =================
__device__ __forceinline__ unsigned f2tf32(float f) {
    unsigned r; asm("cvt.rna.tf32.f32 %0, %1;" : "=r"(r) : "f"(f)); return r;
}

#define MMA_TF32(d, a, b0, b1)                                              \
    asm volatile("mma.sync.aligned.m16n8k8.row.col.f32.tf32.tf32.f32 "      \
                 "{%0,%1,%2,%3}, {%4,%5,%6,%7}, {%8,%9}, {%0,%1,%2,%3};"    \
                 : "+f"(d[0]), "+f"(d[1]), "+f"(d[2]), "+f"(d[3])           \
                 : "r"(a[0]), "r"(a[1]), "r"(a[2]), "r"(a[3]),              \
                   "r"(b0), "r"(b1))

#define BM 128
#define BN 64
#define BK 16
#define APAD 20   // A smem row stride (floats): conflict-free frag loads, 16B-aligned rows
#define BPAD 72   // B smem row stride

__global__ void __launch_bounds__(128) gemm_tf32x3(
    const float* __restrict__ A, const float* __restrict__ B,
    float* __restrict__ C, int M, int K, int N)
{
    __shared__ unsigned Ah[BM * APAD], Al[BM * APAD];
    __shared__ unsigned Bh[BK * BPAD], Bl[BK * BPAD];

    const int tid  = threadIdx.x;
    const int lane = tid & 31;
    const int wid  = tid >> 5;           // 4 warps, each 32 rows x 64 cols
    const int rowBase = blockIdx.y * BM;
    const int colBase = blockIdx.x * BN;

    float c[2][8][4];
#pragma unroll
    for (int mt = 0; mt < 2; mt++)
#pragma unroll
        for (int nt = 0; nt < 8; nt++)
#pragma unroll
            for (int i = 0; i < 4; i++) c[mt][nt][i] = 0.f;

    for (int kt = 0; kt < K; kt += BK) {
        // ---- load A tile [BM x BK] : 512 float4 over 128 threads ----
#pragma unroll
        for (int i = 0; i < 4; i++) {
            int p  = tid + 128 * i;
            int r  = p >> 2;
            int c4 = (p & 3) << 2;
            float4 v = make_float4(0.f, 0.f, 0.f, 0.f);
            int gr = rowBase + r;
            if (gr < M) v = *(const float4*)(A + (size_t)gr * K + kt + c4);
            unsigned hx = f2tf32(v.x), hy = f2tf32(v.y), hz = f2tf32(v.z), hw = f2tf32(v.w);
            unsigned lx = f2tf32(v.x - __uint_as_float(hx));
            unsigned ly = f2tf32(v.y - __uint_as_float(hy));
            unsigned lz = f2tf32(v.z - __uint_as_float(hz));
            unsigned lw = f2tf32(v.w - __uint_as_float(hw));
            int idx = r * APAD + c4;
            *(uint4*)&Ah[idx] = make_uint4(hx, hy, hz, hw);
            *(uint4*)&Al[idx] = make_uint4(lx, ly, lz, lw);
        }
        // ---- load B tile [BK x BN] : 256 float4 over 128 threads ----
#pragma unroll
        for (int i = 0; i < 2; i++) {
            int p  = tid + 128 * i;
            int r  = p >> 4;
            int c4 = (p & 15) << 2;
            float4 v = *(const float4*)(B + (size_t)(kt + r) * N + colBase + c4);
            unsigned hx = f2tf32(v.x), hy = f2tf32(v.y), hz = f2tf32(v.z), hw = f2tf32(v.w);
            unsigned lx = f2tf32(v.x - __uint_as_float(hx));
            unsigned ly = f2tf32(v.y - __uint_as_float(hy));
            unsigned lz = f2tf32(v.z - __uint_as_float(hz));
            unsigned lw = f2tf32(v.w - __uint_as_float(hw));
            int idx = r * BPAD + c4;
            *(uint4*)&Bh[idx] = make_uint4(hx, hy, hz, hw);
            *(uint4*)&Bl[idx] = make_uint4(lx, ly, lz, lw);
        }
        __syncthreads();

#pragma unroll
        for (int ks = 0; ks < BK; ks += 8) {
            unsigned ah[2][4], alr[2][4];
#pragma unroll
            for (int mt = 0; mt < 2; mt++) {
                int r  = wid * 32 + mt * 16 + (lane >> 2);
                int c0 = ks + (lane & 3);
                ah [mt][0] = Ah[r * APAD + c0];
                ah [mt][1] = Ah[(r + 8) * APAD + c0];
                ah [mt][2] = Ah[r * APAD + c0 + 4];
                ah [mt][3] = Ah[(r + 8) * APAD + c0 + 4];
                alr[mt][0] = Al[r * APAD + c0];
                alr[mt][1] = Al[(r + 8) * APAD + c0];
                alr[mt][2] = Al[r * APAD + c0 + 4];
                alr[mt][3] = Al[(r + 8) * APAD + c0 + 4];
            }
#pragma unroll
            for (int nt = 0; nt < 8; nt++) {
                int col = nt * 8 + (lane >> 2);
                int kr  = ks + (lane & 3);
                unsigned bh0 = Bh[kr * BPAD + col], bh1 = Bh[(kr + 4) * BPAD + col];
                unsigned bl0 = Bl[kr * BPAD + col], bl1 = Bl[(kr + 4) * BPAD + col];
#pragma unroll
                for (int mt = 0; mt < 2; mt++) {
                    MMA_TF32(c[mt][nt], ah[mt],  bh0, bh1);
                    MMA_TF32(c[mt][nt], alr[mt], bh0, bh1);
                    MMA_TF32(c[mt][nt], ah[mt],  bl0, bl1);
                }
            }
        }
        __syncthreads();
    }

    // ---- epilogue ----
#pragma unroll
    for (int mt = 0; mt < 2; mt++) {
        int r0 = rowBase + wid * 32 + mt * 16 + (lane >> 2);
        int r1 = r0 + 8;
#pragma unroll
        for (int nt = 0; nt < 8; nt++) {
            int cc = colBase + nt * 8 + (lane & 3) * 2;
            if (r0 < M) *(float2*)(C + (size_t)r0 * N + cc) = make_float2(c[mt][nt][0], c[mt][nt][1]);
            if (r1 < M) *(float2*)(C + (size_t)r1 * N + cc) = make_float2(c[mt][nt][2], c[mt][nt][3]);
        }
    }
}

// ================= attention logits =================
__global__ void attn_logits(const float* __restrict__ feat,
                            const float* __restrict__ al, const float* __restrict__ ar,
                            float* __restrict__ el, float* __restrict__ er)
{
    int n = blockIdx.x;
    int t = threadIdx.x;
    float f = feat[(size_t)n * HID + t];
    float a = f * al[t];
    float b = f * ar[t];
#pragma unroll
    for (int o = 16; o; o >>= 1) {
        a += __shfl_down_sync(0xffffffffu, a, o);
        b += __shfl_down_sync(0xffffffffu, b, o);
    }
    __shared__ float sa[8], sb[8];
    int w = t >> 5;
    if ((t & 31) == 0) { sa[w] = a; sb[w] = b; }
    __syncthreads();
    if (t < 4) {
        el[(size_t)n * HH + t] = sa[2 * t] + sa[2 * t + 1];
        er[(size_t)n * HH + t] = sb[2 * t] + sb[2 * t + 1];
    }
}

// ================= CSR build (once per launch; edges shared by all layers) =================
__global__ void hist_k(const int* __restrict__ dst, int* deg, int E)
{
    int i = blockIdx.x * blockDim.x + threadIdx.x;
    if (i < E) atomicAdd(&deg[dst[i]], 1);
}

__global__ void scan_k(const int* __restrict__ deg, int* __restrict__ rowptr, int n, int E)
{
    const int C = (n + 1023) >> 10;
    int t = threadIdx.x;
    int base = t * C;
    int s = 0;
    for (int i = 0; i < C; i++) { int id = base + i; if (id < n) s += deg[id]; }
    __shared__ int sm[1024];
    sm[t] = s;
    __syncthreads();
    for (int off = 1; off < 1024; off <<= 1) {
        int v = (t >= off) ? sm[t - off] : 0;
        __syncthreads();
        sm[t] += v;
        __syncthreads();
    }
    int run = sm[t] - s;   // exclusive prefix
    for (int i = 0; i < C; i++) {
        int id = base + i;
        if (id < n) { rowptr[id] = run; run += deg[id]; }
    }
    if (t == 0) rowptr[n] = E;
}

__global__ void scatter_k(const int* __restrict__ src, const int* __restrict__ dst,
                          int* cursor, int* __restrict__ esrc, int E)
{
    int i = blockIdx.x * blockDim.x + threadIdx.x;
    if (i >= E) return;
    int p = atomicAdd(&cursor[dst[i]], 1);
    esrc[p] = src[i];
}

// ================= fused per-node GAT aggregation (warp per dst node) =================
// out = relu( sum_i w_i feat[src_i] / sum_i w_i + res + b )          (MODE 0)
// out = mean_h( sum_i w_i feat[src_i] / sum_i w_i + res + b )        (MODE 2, [N,DH])
template<int MODE>
__global__ void gat_node_k(const float* __restrict__ feat,
                           const int* __restrict__ rowptr, const int* __restrict__ esrc,
                           const float* __restrict__ el, const float* __restrict__ er,
                           const float* __restrict__ res, const float* __restrict__ bias,
                           float* __restrict__ out)
{
    int warp = (blockIdx.x * blockDim.x + threadIdx.x) >> 5;
    if (warp >= NN) return;
    int lane = threadIdx.x & 31;
    int start = rowptr[warp], end = rowptr[warp + 1];
    int cnt = end - start;

    // pass 1: per-head max (lane handles head lane&3; stride-32 keeps head fixed)
    int hA = lane & 3;
    float erA = er[(size_t)warp * HH + hA];
    float m = -1e30f;
    for (int j = lane; j < cnt * HH; j += 32) {
        int s = esrc[start + (j >> 2)];
        float v = el[(size_t)s * HH + hA] + erA;
        v = v > 0.f ? v : 0.2f * v;
        m = fmaxf(m, v);
    }
#pragma unroll
    for (int off = 4; off < 32; off <<= 1) m = fmaxf(m, __shfl_xor_sync(0xffffffffu, m, off));

    // pass 2: lane owns 8 feature columns [lane*8, lane*8+8); head hB = lane>>3
    int hB = lane >> 3;
    float m2  = __shfl_sync(0xffffffffu, m, hB);   // lanes 0..3 hold heads 0..3
    float erB = er[(size_t)warp * HH + hB];

    float a0 = 0, a1 = 0, a2 = 0, a3 = 0, a4 = 0, a5 = 0, a6 = 0, a7 = 0;
    float den = 0.f;
    for (int idx = start; idx < end; idx++) {
        int s = esrc[idx];
        float v = el[(size_t)s * HH + hB] + erB;
        v = v > 0.f ? v : 0.2f * v;
        float w = __expf(v - m2);
        den += w;
        const float4* fp = (const float4*)(feat + (size_t)s * HID + lane * 8);
        float4 f0 = fp[0], f1 = fp[1];
        a0 += w * f0.x; a1 += w * f0.y; a2 += w * f0.z; a3 += w * f0.w;
        a4 += w * f1.x; a5 += w * f1.y; a6 += w * f1.z; a7 += w * f1.w;
    }
    float inv = 1.f / fmaxf(den, 1e-16f);

    size_t o = (size_t)warp * HID + lane * 8;
    float4 r0 = *(const float4*)(res + o);
    float4 r1 = *(const float4*)(res + o + 4);
    float4 b0 = *(const float4*)(bias + lane * 8);
    float4 b1 = *(const float4*)(bias + lane * 8 + 4);

    float v0 = a0 * inv + r0.x + b0.x;
    float v1 = a1 * inv + r0.y + b0.y;
    float v2 = a2 * inv + r0.z + b0.z;
    float v3 = a3 * inv + r0.w + b0.w;
    float v4 = a4 * inv + r1.x + b1.x;
    float v5 = a5 * inv + r1.y + b1.y;
    float v6 = a6 * inv + r1.z + b1.z;
    float v7 = a7 * inv + r1.w + b1.w;

    if (MODE == 0) {
        float4 s0 = make_float4(fmaxf(v0, 0.f), fmaxf(v1, 0.f), fmaxf(v2, 0.f), fmaxf(v3, 0.f));
        float4 s1 = make_float4(fmaxf(v4, 0.f), fmaxf(v5, 0.f), fmaxf(v6, 0.f), fmaxf(v7, 0.f));
        *(float4*)(out + o)     = s0;
        *(float4*)(out + o + 4) = s1;
    } else {
        // mean over heads: lanes l, l^8, l^16, l^24 hold the same within-head column
#pragma unroll
        for (int off = 8; off < 32; off <<= 1) {
            v0 += __shfl_xor_sync(0xffffffffu, v0, off);
            v1 += __shfl_xor_sync(0xffffffffu, v1, off);
            v2 += __shfl_xor_sync(0xffffffffu, v2, off);
            v3 += __shfl_xor_sync(0xffffffffu, v3, off);
            v4 += __shfl_xor_sync(0xffffffffu, v4, off);
            v5 += __shfl_xor_sync(0xffffffffu, v5, off);
            v6 += __shfl_xor_sync(0xffffffffu, v6, off);
            v7 += __shfl_xor_sync(0xffffffffu, v7, off);
        }
        if (lane < 8) {
            size_t oy = (size_t)warp * DHH + lane * 8;
            *(float4*)(out + oy)     = make_float4(v0 * 0.25f, v1 * 0.25f, v2 * 0.25f, v3 * 0.25f);
            *(float4*)(out + oy + 4) = make_float4(v4 * 0.25f, v5 * 0.25f, v6 * 0.25f, v7 * 0.25f);
        }
    }
}

// ================= host orchestration =================
extern "C" void kernel_launch(void* const* d_in, const int* in_sizes, int n_in,
                              void* d_out, int out_size)
{
    const float* x  = (const float*)d_in[0];
    const int*   ei = (const int*)d_in[1];
    const int E  = in_sizes[1] / 2;
    const int Nn = in_sizes[0] / FIN;
    const int* src = ei;
    const int* dst = ei + E;
    const float* W[3]  = {(const float*)d_in[2],  (const float*)d_in[3],  (const float*)d_in[4]};
    const float* al[3] = {(const float*)d_in[5],  (const float*)d_in[6],  (const float*)d_in[7]};
    const float* ar[3] = {(const float*)d_in[8],  (const float*)d_in[9],  (const float*)d_in[10]};
    const float* bb[3] = {(const float*)d_in[11], (const float*)d_in[12], (const float*)d_in[13]};
    const float* resW0 = (const float*)d_in[14];

    float *feat, *res, *h1, *h2, *el, *er;
    int *deg, *rowptr, *cursor, *esrc;
    cudaGetSymbolAddress((void**)&feat,   g_feat);
    cudaGetSymbolAddress((void**)&res,    g_res);
    cudaGetSymbolAddress((void**)&h1,     g_h1);
    cudaGetSymbolAddress((void**)&h2,     g_h2);
    cudaGetSymbolAddress((void**)&el,     g_el);
    cudaGetSymbolAddress((void**)&er,     g_er);
    cudaGetSymbolAddress((void**)&deg,    g_deg);
    cudaGetSymbolAddress((void**)&rowptr, g_rowptr);
    cudaGetSymbolAddress((void**)&cursor, g_cursor);
    cudaGetSymbolAddress((void**)&esrc,   g_esrc);

    const dim3 gemmGrid(HID / BN, (Nn + BM - 1) / BM);
    const int nodeGrid = (Nn + 7) / 8;   // 8 warps/block

    // ---- CSR by dst (edges identical for all 3 layers) ----
    cudaMemsetAsync(deg, 0, (size_t)Nn * sizeof(int), 0);
    hist_k<<<(E + 255) / 256, 256>>>(dst, deg, E);
    scan_k<<<1, 1024>>>(deg, rowptr, Nn, E);
    cudaMemcpyAsync(cursor, rowptr, (size_t)Nn * sizeof(int), cudaMemcpyDeviceToDevice, 0);
    scatter_k<<<(E + 255) / 256, 256>>>(src, dst, cursor, esrc, E);

    // ---- Layer 0 ----
    gemm_tf32x3<<<gemmGrid, 128>>>(x, W[0],  feat, Nn, FIN, HID);
    gemm_tf32x3<<<gemmGrid, 128>>>(x, resW0, res,  Nn, FIN, HID);
    attn_logits<<<Nn, 256>>>(feat, al[0], ar[0], el, er);
    gat_node_k<0><<<nodeGrid, 256>>>(feat, rowptr, esrc, el, er, res, bb[0], h1);

    // ---- Layer 1 ----
    gemm_tf32x3<<<gemmGrid, 128>>>(h1, W[1], feat, Nn, HID, HID);
    attn_logits<<<Nn, 256>>>(feat, al[1], ar[1], el, er);
    gat_node_k<0><<<nodeGrid, 256>>>(feat, rowptr, esrc, el, er, h1, bb[1], h2);

    // ---- Layer 2 ----
    gemm_tf32x3<<<gemmGrid, 128>>>(h2, W[2], feat, Nn, HID, HID);
    attn_logits<<<Nn, 256>>>(feat, al[2], ar[2], el, er);
    gat_node_k<2><<<nodeGrid, 256>>>(feat, rowptr, esrc, el, er, h2, bb[2], (float*)d_out);
}

// round 3
// speedup vs baseline: 1.9342x; 1.0625x over previous
#include <cuda_runtime.h>
#include <cstdint>

// Problem constants (fixed by the dataset)
#define NN   50000
#define EE   800000
#define FIN  128
#define HH   4
#define DHH  64
#define HID  256   // HH*DHH

// ---------------- static device scratch ----------------
__device__ float    g_feat[(size_t)NN * HID];
__device__ float    g_res [(size_t)NN * HID];
__device__ float    g_h1  [(size_t)NN * HID];
__device__ float    g_h2  [(size_t)NN * HID];
__device__ float    g_el  [(size_t)NN * HH];
__device__ float    g_er  [(size_t)NN * HH];
__device__ unsigned g_menc[(size_t)NN * HH];
__device__ unsigned g_Bh  [(size_t)HID * HID];
__device__ unsigned g_Bl  [(size_t)HID * HID];
__device__ int      g_deg   [NN];
__device__ int      g_rowptr[NN + 1];
__device__ int      g_cursor[NN];
__device__ int      g_esrc  [EE];

__device__ __forceinline__ unsigned f2tf32(float f) {
    unsigned r; asm("cvt.rna.tf32.f32 %0, %1;" : "=r"(r) : "f"(f)); return r;
}
__device__ __forceinline__ unsigned enc_f(float v) {
    unsigned b = __float_as_uint(v);
    return (b & 0x80000000u) ? ~b : (b | 0x80000000u);
}
__device__ __forceinline__ float dec_f(unsigned u) {
    unsigned b = (u & 0x80000000u) ? (u ^ 0x80000000u) : ~u;
    return __uint_as_float(b);
}

// ================= B pre-conversion: W[K*N] -> tf32 hi/lo =================
__global__ void convW_k(const float* __restrict__ W, unsigned* __restrict__ Bh,
                        unsigned* __restrict__ Bl, int n)
{
    int i = blockIdx.x * blockDim.x + threadIdx.x;
    if (i >= n) return;
    float w = W[i];
    unsigned h = f2tf32(w);
    Bh[i] = h;
    Bl[i] = f2tf32(w - __uint_as_float(h));
}

// ================= GEMM: C[M,N] = A @ B (3xTF32), fused el/er epilogue =================
#define MMA_TF32(d, a, b0, b1)                                              \
    asm volatile("mma.sync.aligned.m16n8k8.row.col.f32.tf32.tf32.f32 "      \
                 "{%0,%1,%2,%3}, {%4,%5,%6,%7}, {%8,%9}, {%0,%1,%2,%3};"    \
                 : "+f"(d[0]), "+f"(d[1]), "+f"(d[2]), "+f"(d[3])           \
                 : "r"(a[0]), "r"(a[1]), "r"(a[2]), "r"(a[3]),              \
                   "r"(b0), "r"(b1))

#define BM 128
#define BN 64
#define BK 16
#define APAD 20
#define BPAD 72

template<bool FUSE>
__global__ void __launch_bounds__(128) gemm_tf32x3(
    const float* __restrict__ A,
    const unsigned* __restrict__ Bhg, const unsigned* __restrict__ Blg,
    float* __restrict__ C,
    const float* __restrict__ al, const float* __restrict__ ar,
    float* __restrict__ el, float* __restrict__ er,
    int M, int K, int N)
{
    __shared__ unsigned Ah[BM * APAD], Al[BM * APAD];
    __shared__ unsigned Bh[BK * BPAD], Bl[BK * BPAD];

    const int tid  = threadIdx.x;
    const int lane = tid & 31;
    const int wid  = tid >> 5;
    const int rowBase = blockIdx.y * BM;
    const int colBase = blockIdx.x * BN;

    float c[2][8][4];
#pragma unroll
    for (int mt = 0; mt < 2; mt++)
#pragma unroll
        for (int nt = 0; nt < 8; nt++)
#pragma unroll
            for (int i = 0; i < 4; i++) c[mt][nt][i] = 0.f;

    // staged tiles
    float4 av[4];
    uint4  bhv[2], blv[2];

    const int aRow  = tid >> 2;
    const int aCol4 = (tid & 3) << 2;
    const int bRow2 = tid >> 4;
    const int bCol4 = (tid & 15) << 2;

    auto ldgA = [&](int kt) {
#pragma unroll
        for (int i = 0; i < 4; i++) {
            int r  = aRow + 32 * i;
            int gr = rowBase + r;
            av[i] = (gr < M) ? *(const float4*)(A + (size_t)gr * K + kt + aCol4)
                             : make_float4(0.f, 0.f, 0.f, 0.f);
        }
    };
    auto ldgB = [&](int kt) {
#pragma unroll
        for (int i = 0; i < 2; i++) {
            int r = bRow2 + 8 * i;
            size_t off = (size_t)(kt + r) * N + colBase + bCol4;
            bhv[i] = *(const uint4*)(Bhg + off);
            blv[i] = *(const uint4*)(Blg + off);
        }
    };
    auto stsAB = [&]() {
#pragma unroll
        for (int i = 0; i < 4; i++) {
            int r = aRow + 32 * i;
            unsigned hx = f2tf32(av[i].x), hy = f2tf32(av[i].y),
                     hz = f2tf32(av[i].z), hw = f2tf32(av[i].w);
            unsigned lx = f2tf32(av[i].x - __uint_as_float(hx));
            unsigned ly = f2tf32(av[i].y - __uint_as_float(hy));
            unsigned lz = f2tf32(av[i].z - __uint_as_float(hz));
            unsigned lw = f2tf32(av[i].w - __uint_as_float(hw));
            int idx = r * APAD + aCol4;
            *(uint4*)&Ah[idx] = make_uint4(hx, hy, hz, hw);
            *(uint4*)&Al[idx] = make_uint4(lx, ly, lz, lw);
        }
#pragma unroll
        for (int i = 0; i < 2; i++) {
            int idx = (bRow2 + 8 * i) * BPAD + bCol4;
            *(uint4*)&Bh[idx] = bhv[i];
            *(uint4*)&Bl[idx] = blv[i];
        }
    };

    ldgA(0); ldgB(0);
    const int ntiles = K / BK;
    for (int t = 0; t < ntiles; t++) {
        stsAB();
        __syncthreads();
        if (t + 1 < ntiles) { ldgA((t + 1) * BK); ldgB((t + 1) * BK); }

#pragma unroll
        for (int ks = 0; ks < BK; ks += 8) {
            unsigned ah[2][4], alr[2][4];
#pragma unroll
            for (int mt = 0; mt < 2; mt++) {
                int r  = wid * 32 + mt * 16 + (lane >> 2);
                int c0 = ks + (lane & 3);
                ah [mt][0] = Ah[r * APAD + c0];
                ah [mt][1] = Ah[(r + 8) * APAD + c0];
                ah [mt][2] = Ah[r * APAD + c0 + 4];
                ah [mt][3] = Ah[(r + 8) * APAD + c0 + 4];
                alr[mt][0] = Al[r * APAD + c0];
                alr[mt][1] = Al[(r + 8) * APAD + c0];
                alr[mt][2] = Al[r * APAD + c0 + 4];
                alr[mt][3] = Al[(r + 8) * APAD + c0 + 4];
            }
#pragma unroll
            for (int nt = 0; nt < 8; nt++) {
                int col = nt * 8 + (lane >> 2);
                int kr  = ks + (lane & 3);
                unsigned bh0 = Bh[kr * BPAD + col], bh1 = Bh[(kr + 4) * BPAD + col];
                unsigned bl0 = Bl[kr * BPAD + col], bl1 = Bl[(kr + 4) * BPAD + col];
#pragma unroll
                for (int mt = 0; mt < 2; mt++) {
                    MMA_TF32(c[mt][nt], ah[mt],  bh0, bh1);
                    MMA_TF32(c[mt][nt], alr[mt], bh0, bh1);
                    MMA_TF32(c[mt][nt], ah[mt],  bl0, bl1);
                }
            }
        }
        __syncthreads();
    }

    // ---- store C ----
#pragma unroll
    for (int mt = 0; mt < 2; mt++) {
        int r0 = rowBase + wid * 32 + mt * 16 + (lane >> 2);
        int r1 = r0 + 8;
#pragma unroll
        for (int nt = 0; nt < 8; nt++) {
            int cc = colBase + nt * 8 + (lane & 3) * 2;
            if (r0 < M) *(float2*)(C + (size_t)r0 * N + cc) = make_float2(c[mt][nt][0], c[mt][nt][1]);
            if (r1 < M) *(float2*)(C + (size_t)r1 * N + cc) = make_float2(c[mt][nt][2], c[mt][nt][3]);
        }
    }

    // ---- fused el/er: this col-block is exactly head h = blockIdx.x ----
    if (FUSE) {
        int h = blockIdx.x;
        float alv[16], arv[16];
#pragma unroll
        for (int nt = 0; nt < 8; nt++)
#pragma unroll
            for (int j = 0; j < 2; j++) {
                int cc = nt * 8 + (lane & 3) * 2 + j;
                alv[nt * 2 + j] = al[h * 64 + cc];
                arv[nt * 2 + j] = ar[h * 64 + cc];
            }
#pragma unroll
        for (int mt = 0; mt < 2; mt++) {
            float e0 = 0, e1 = 0, f0 = 0, f1 = 0;
#pragma unroll
            for (int nt = 0; nt < 8; nt++)
#pragma unroll
                for (int j = 0; j < 2; j++) {
                    e0 += c[mt][nt][j]     * alv[nt * 2 + j];
                    e1 += c[mt][nt][2 + j] * alv[nt * 2 + j];
                    f0 += c[mt][nt][j]     * arv[nt * 2 + j];
                    f1 += c[mt][nt][2 + j] * arv[nt * 2 + j];
                }
#pragma unroll
            for (int off = 1; off < 4; off <<= 1) {
                e0 += __shfl_xor_sync(0xffffffffu, e0, off);
                e1 += __shfl_xor_sync(0xffffffffu, e1, off);
                f0 += __shfl_xor_sync(0xffffffffu, f0, off);
                f1 += __shfl_xor_sync(0xffffffffu, f1, off);
            }
            if ((lane & 3) == 0) {
                int r0 = rowBase + wid * 32 + mt * 16 + (lane >> 2);
                int r1 = r0 + 8;
                if (r0 < M) { el[(size_t)r0 * HH + h] = e0; er[(size_t)r0 * HH + h] = f0; }
                if (r1 < M) { el[(size_t)r1 * HH + h] = e1; er[(size_t)r1 * HH + h] = f1; }
            }
        }
    }
}

// ================= CSR build (once; edges shared by all layers) =================
__global__ void hist_k(const int* __restrict__ dst, int* deg, int E)
{
    int i = blockIdx.x * blockDim.x + threadIdx.x;
    if (i < E) atomicAdd(&deg[dst[i]], 1);
}

__global__ void scan_k(const int* __restrict__ deg, int* __restrict__ rowptr, int n, int E)
{
    const int C = (n + 1023) >> 10;
    int t = threadIdx.x;
    int base = t * C;
    int s = 0;
    for (int i = 0; i < C; i++) { int id = base + i; if (id < n) s += deg[id]; }
    __shared__ int sm[1024];
    sm[t] = s;
    __syncthreads();
    for (int off = 1; off < 1024; off <<= 1) {
        int v = (t >= off) ? sm[t - off] : 0;
        __syncthreads();
        sm[t] += v;
        __syncthreads();
    }
    int run = sm[t] - s;
    for (int i = 0; i < C; i++) {
        int id = base + i;
        if (id < n) { rowptr[id] = run; run += deg[id]; }
    }
    if (t == 0) rowptr[n] = E;
}

__global__ void scatter_k(const int* __restrict__ src, const int* __restrict__ dst,
                          int* cursor, int* __restrict__ esrc, int E)
{
    int i = blockIdx.x * blockDim.x + threadIdx.x;
    if (i >= E) return;
    int p = atomicAdd(&cursor[dst[i]], 1);
    esrc[p] = src[i];
}

// ================= edge-parallel per-(dst,head) max =================
__global__ void edge_max_k(const int* __restrict__ src, const int* __restrict__ dst,
                           const float* __restrict__ el, const float* __restrict__ er,
                           unsigned* __restrict__ menc, int EH)
{
    int i = blockIdx.x * blockDim.x + threadIdx.x;
    if (i >= EH) return;
    int e = i >> 2, h = i & 3;
    int s = src[e], d = dst[e];
    float v = el[(size_t)s * HH + h] + er[(size_t)d * HH + h];
    v = (v > 0.f) ? v : 0.2f * v;
    atomicMax(&menc[(size_t)d * HH + h], enc_f(v));
}

// ================= single-pass per-node GAT aggregation (warp/node) =================
template<int MODE>
__global__ void gat_node_k(const float* __restrict__ feat,
                           const int* __restrict__ rowptr, const int* __restrict__ esrc,
                           const float* __restrict__ el, const float* __restrict__ er,
                           const unsigned* __restrict__ menc,
                           const float* __restrict__ res, const float* __restrict__ bias,
                           float* __restrict__ out)
{
    int warp = (blockIdx.x * blockDim.x + threadIdx.x) >> 5;
    if (warp >= NN) return;
    int lane = threadIdx.x & 31;
    int start = rowptr[warp], end = rowptr[warp + 1];

    int hB = lane >> 3;
    unsigned u = menc[(size_t)warp * HH + hB];
    float m   = u ? dec_f(u) : 0.f;
    float erB = er[(size_t)warp * HH + hB];

    float a0 = 0, a1 = 0, a2 = 0, a3 = 0, a4 = 0, a5 = 0, a6 = 0, a7 = 0;
    float den = 0.f;

    const float4* fbase = (const float4*)feat;
    int idx = start;
    for (; idx + 2 <= end; idx += 2) {
        int s0 = esrc[idx], s1 = esrc[idx + 1];
        float e0 = el[(size_t)s0 * HH + hB];
        float e1 = el[(size_t)s1 * HH + hB];
        const float4* p0 = fbase + (size_t)s0 * 64 + lane * 2;
        const float4* p1 = fbase + (size_t)s1 * 64 + lane * 2;
        float4 x0 = p0[0], x1 = p0[1];
        float4 y0 = p1[0], y1 = p1[1];
        float v0 = e0 + erB; v0 = v0 > 0.f ? v0 : 0.2f * v0;
        float v1 = e1 + erB; v1 = v1 > 0.f ? v1 : 0.2f * v1;
        float w0 = __expf(v0 - m);
        float w1 = __expf(v1 - m);
        den += w0 + w1;
        a0 += w0 * x0.x; a1 += w0 * x0.y; a2 += w0 * x0.z; a3 += w0 * x0.w;
        a4 += w0 * x1.x; a5 += w0 * x1.y; a6 += w0 * x1.z; a7 += w0 * x1.w;
        a0 += w1 * y0.x; a1 += w1 * y0.y; a2 += w1 * y0.z; a3 += w1 * y0.w;
        a4 += w1 * y1.x; a5 += w1 * y1.y; a6 += w1 * y1.z; a7 += w1 * y1.w;
    }
    if (idx < end) {
        int s0 = esrc[idx];
        float e0 = el[(size_t)s0 * HH + hB];
        const float4* p0 = fbase + (size_t)s0 * 64 + lane * 2;
        float4 x0 = p0[0], x1 = p0[1];
        float v0 = e0 + erB; v0 = v0 > 0.f ? v0 : 0.2f * v0;
        float w0 = __expf(v0 - m);
        den += w0;
        a0 += w0 * x0.x; a1 += w0 * x0.y; a2 += w0 * x0.z; a3 += w0 * x0.w;
        a4 += w0 * x1.x; a5 += w0 * x1.y; a6 += w0 * x1.z; a7 += w0 * x1.w;
    }
    float inv = 1.f / fmaxf(den, 1e-16f);

    size_t o = (size_t)warp * HID + lane * 8;
    float4 r0 = *(const float4*)(res + o);
    float4 r1 = *(const float4*)(res + o + 4);
    float4 b0 = *(const float4*)(bias + lane * 8);
    float4 b1 = *(const float4*)(bias + lane * 8 + 4);

    float v0 = a0 * inv + r0.x + b0.x;
    float v1 = a1 * inv + r0.y + b0.y;
    float v2 = a2 * inv + r0.z + b0.z;
    float v3 = a3 * inv + r0.w + b0.w;
    float v4 = a4 * inv + r1.x + b1.x;
    float v5 = a5 * inv + r1.y + b1.y;
    float v6 = a6 * inv + r1.z + b1.z;
    float v7 = a7 * inv + r1.w + b1.w;

    if (MODE == 0) {
        *(float4*)(out + o)     = make_float4(fmaxf(v0, 0.f), fmaxf(v1, 0.f), fmaxf(v2, 0.f), fmaxf(v3, 0.f));
        *(float4*)(out + o + 4) = make_float4(fmaxf(v4, 0.f), fmaxf(v5, 0.f), fmaxf(v6, 0.f), fmaxf(v7, 0.f));
    } else {
#pragma unroll
        for (int off = 8; off < 32; off <<= 1) {
            v0 += __shfl_xor_sync(0xffffffffu, v0, off);
            v1 += __shfl_xor_sync(0xffffffffu, v1, off);
            v2 += __shfl_xor_sync(0xffffffffu, v2, off);
            v3 += __shfl_xor_sync(0xffffffffu, v3, off);
            v4 += __shfl_xor_sync(0xffffffffu, v4, off);
            v5 += __shfl_xor_sync(0xffffffffu, v5, off);
            v6 += __shfl_xor_sync(0xffffffffu, v6, off);
            v7 += __shfl_xor_sync(0xffffffffu, v7, off);
        }
        if (lane < 8) {
            size_t oy = (size_t)warp * DHH + lane * 8;
            *(float4*)(out + oy)     = make_float4(v0 * 0.25f, v1 * 0.25f, v2 * 0.25f, v3 * 0.25f);
            *(float4*)(out + oy + 4) = make_float4(v4 * 0.25f, v5 * 0.25f, v6 * 0.25f, v7 * 0.25f);
        }
    }
}

// ================= host orchestration =================
extern "C" void kernel_launch(void* const* d_in, const int* in_sizes, int n_in,
                              void* d_out, int out_size)
{
    const float* x  = (const float*)d_in[0];
    const int*   ei = (const int*)d_in[1];
    const int E  = in_sizes[1] / 2;
    const int Nn = in_sizes[0] / FIN;
    const int* src = ei;
    const int* dst = ei + E;
    const float* W[3]  = {(const float*)d_in[2],  (const float*)d_in[3],  (const float*)d_in[4]};
    const float* al[3] = {(const float*)d_in[5],  (const float*)d_in[6],  (const float*)d_in[7]};
    const float* ar[3] = {(const float*)d_in[8],  (const float*)d_in[9],  (const float*)d_in[10]};
    const float* bb[3] = {(const float*)d_in[11], (const float*)d_in[12], (const float*)d_in[13]};
    const float* resW0 = (const float*)d_in[14];

    float *feat, *res, *h1, *h2, *el, *er;
    unsigned *menc, *Bh, *Bl;
    int *deg, *rowptr, *cursor, *esrc;
    cudaGetSymbolAddress((void**)&feat,   g_feat);
    cudaGetSymbolAddress((void**)&res,    g_res);
    cudaGetSymbolAddress((void**)&h1,     g_h1);
    cudaGetSymbolAddress((void**)&h2,     g_h2);
    cudaGetSymbolAddress((void**)&el,     g_el);
    cudaGetSymbolAddress((void**)&er,     g_er);
    cudaGetSymbolAddress((void**)&menc,   g_menc);
    cudaGetSymbolAddress((void**)&Bh,     g_Bh);
    cudaGetSymbolAddress((void**)&Bl,     g_Bl);
    cudaGetSymbolAddress((void**)&deg,    g_deg);
    cudaGetSymbolAddress((void**)&rowptr, g_rowptr);
    cudaGetSymbolAddress((void**)&cursor, g_cursor);
    cudaGetSymbolAddress((void**)&esrc,   g_esrc);

    const dim3 gemmGrid(HID / BN, (Nn + BM - 1) / BM);
    const int nodeGrid = (Nn + 7) / 8;
    const int EH = E * HH;
    const int NH = Nn * HH;

    // ---- CSR by dst (edges identical for all 3 layers) ----
    cudaMemsetAsync(deg, 0, (size_t)Nn * sizeof(int), 0);
    hist_k<<<(E + 255) / 256, 256>>>(dst, deg, E);
    scan_k<<<1, 1024>>>(deg, rowptr, Nn, E);
    cudaMemcpyAsync(cursor, rowptr, (size_t)Nn * sizeof(int), cudaMemcpyDeviceToDevice, 0);
    scatter_k<<<(E + 255) / 256, 256>>>(src, dst, cursor, esrc, E);

    auto layer = [&](const float* A, int K, const float* Wc, const float* alc, const float* arc) {
        convW_k<<<(K * HID + 255) / 256, 256>>>(Wc, Bh, Bl, K * HID);
        gemm_tf32x3<true><<<gemmGrid, 128>>>(A, Bh, Bl, feat, alc, arc, el, er, Nn, K, HID);
        cudaMemsetAsync(menc, 0, (size_t)NH * sizeof(unsigned), 0);
        edge_max_k<<<(EH + 255) / 256, 256>>>(src, dst, el, er, menc, EH);
    };

    // ---- Layer 0 ----
    layer(x, FIN, W[0], al[0], ar[0]);
    convW_k<<<(FIN * HID + 255) / 256, 256>>>(resW0, Bh, Bl, FIN * HID);
    gemm_tf32x3<false><<<gemmGrid, 128>>>(x, Bh, Bl, res, nullptr, nullptr, nullptr, nullptr, Nn, FIN, HID);
    gat_node_k<0><<<nodeGrid, 256>>>(feat, rowptr, esrc, el, er, menc, res, bb[0], h1);

    // ---- Layer 1 ----
    layer(h1, HID, W[1], al[1], ar[1]);
    gat_node_k<0><<<nodeGrid, 256>>>(feat, rowptr, esrc, el, er, menc, h1, bb[1], h2);

    // ---- Layer 2 ----
    layer(h2, HID, W[2], al[2], ar[2]);
    gat_node_k<2><<<nodeGrid, 256>>>(feat, rowptr, esrc, el, er, menc, h2, bb[2], (float*)d_out);
}